// round 14
// baseline (speedup 1.0000x reference)
#include <cuda_runtime.h>
#include <cuda_fp16.h>

// BlurNet: fake_B = w * mean_k bilinear(fake_S, pix + t_k*20*blurmap) + bias
//          offsets_flat[b, 2k+c] = t_k * 20 * blurmap[b, c],  t_k = (7-k)/7
// B=8, C=3, H=W=256. Output: fake_B (B*3*H*W) then offsets (B*30*H*W), f32.
//
// R14 = R13 body (64x32 tile, fp16 pair-dup gather, half2 lerp, interleaved
// offset STGs) at 256 threads / 128 regs: R13 showed issue 47% / L1 65% with
// flat dur => LDS-latency-bound. Occupancy is register-capped (32 warps x 64
// regs = full RF), so the only latency lever left is per-warp MLP: 128 regs
// lets ptxas front-batch LDS across the unrolled 14-sample loop instead of
// ~2-3 samples at a time. 16 warps/SM, 8 px/thread.

#define H 256
#define W 256
#define HW (H * W)
#define BATCH 8
#define TX 64
#define TY 32
#define HALO 20
#define TDX (TX + 2 * HALO)      // 104
#define TDY (TY + 2 * HALO)      // 72
#define NTHREADS 256

__global__ __launch_bounds__(NTHREADS, 2)
void blurnet_kernel(const float* __restrict__ fake_S,
                    const float* __restrict__ blurmap,
                    const float* __restrict__ weight,
                    const float* __restrict__ bias,
                    float* __restrict__ out_fb,
                    float* __restrict__ out_off)
{
    extern __shared__ __align__(16) unsigned char smem_raw[];
    uint2*   Ap = (uint2*)smem_raw;                         // 72*104*8 = 59904 B
    __half2* Cp = (__half2*)(smem_raw + TDY * TDX * 8);     // 72*104*4 = 29952 B

    const int tx0 = blockIdx.x * TX;
    const int ty0 = blockIdx.y * TY;
    const int b   = blockIdx.z;
    const int tid = threadIdx.x;

    const float* img  = fake_S  + (size_t)b * 3 * HW;
    const float* bm   = blurmap + (size_t)b * 2 * HW;
    float*       fb   = out_fb  + (size_t)b * 3 * HW;
    float*       offp = out_off + (size_t)b * 30 * HW;

    // ---- Halo fill: R3-proven scalar path ----
    #pragma unroll 3
    for (int p = tid; p < TDY * TDX; p += NTHREADS) {
        int r  = p / TDX;
        int cc = p - r * TDX;
        int gy = ty0 - HALO + r;
        int gx = tx0 - HALO + cc;
        float v0 = 0.f, v1 = 0.f, v2 = 0.f;   // (gy, gx)
        float u0 = 0.f, u1 = 0.f, u2 = 0.f;   // (gy, gx+1)
        bool rowok = (unsigned)gy < (unsigned)H;
        if (rowok && (unsigned)gx < (unsigned)W) {
            int gi = gy * W + gx;
            v0 = __ldg(img + gi);
            v1 = __ldg(img + gi + HW);
            v2 = __ldg(img + gi + 2 * HW);
        }
        if (rowok && (unsigned)(gx + 1) < (unsigned)W) {
            int gi = gy * W + gx + 1;
            u0 = __ldg(img + gi);
            u1 = __ldg(img + gi + HW);
            u2 = __ldg(img + gi + 2 * HW);
        }
        __half2 lo = __floats2half2_rn(v0, v1);
        __half2 hi = __floats2half2_rn(u0, u1);
        uint2 w;
        w.x = *(unsigned int*)&lo;
        w.y = *(unsigned int*)&hi;
        Ap[p] = w;
        Cp[p] = __floats2half2_rn(v2, u2);
    }
    __syncthreads();

    const float wgt = __ldg(weight) * (1.0f / 15.0f);
    const float bs  = __ldg(bias);

    // ---- Blur loop: 8 px/thread, half2 lerp, interleaved offset stores ----
    #pragma unroll 1
    for (int i = 0; i < (TX * TY) / NTHREADS; i++) {
        int p  = i * NTHREADS + tid;
        int yl = p >> 6;              // 0..31
        int xl = p & 63;              // 0..63
        int gy = ty0 + yl;
        int gx = tx0 + xl;
        int gidx = gy * W + gx;

        float ob0 = 20.0f * __ldg(bm + gidx);        // dy scale (ch0)
        float ob1 = 20.0f * __ldg(bm + gidx + HW);   // dx scale (ch1)

        // k = 7 (t = 0): exact center sample, zero offsets
        int cbase = (yl + HALO) * TDX + (xl + HALO);
        uint2 cw = Ap[cbase];
        float2 cl = __half22float2(*(__half2*)&cw.x);
        float2 cz = __half22float2(Cp[cbase]);
        float s0 = cl.x, s1 = cl.y, s2 = cz.x;
        offp[14 * HW + gidx] = 0.f;
        offp[15 * HW + gidx] = 0.f;

        #pragma unroll
        for (int k = 0; k < 15; k++) {
            if (k == 7) continue;
            const float t = (float)(7 - k) / 7.0f;   // compile-time constant
            float oy = t * ob0;
            float ox = t * ob1;
            offp[(2 * k) * HW + gidx]     = oy;
            offp[(2 * k + 1) * HW + gidx] = ox;

            float fy  = (float)gy + oy;              // global coords = ref rounding
            float fx  = (float)gx + ox;
            float fy0 = floorf(fy);
            float fx0 = floorf(fx);
            float tyf = fy - fy0;
            float txf = fx - fx0;
            int iy = (int)fy0 - ty0 + HALO;
            int ix = (int)fx0 - tx0 + HALO;
            int base2 = iy * TDX + ix;

            uint2   w0 = Ap[base2];           // row y0: (c0,c1)@x0,x1
            uint2   w1 = Ap[base2 + TDX];     // row y1
            __half2 z0 = Cp[base2];           // c2@(x0,x1), row y0
            __half2 z1 = Cp[base2 + TDX];     // row y1

            __half2 txh = __float2half2_rn(txf);
            __half2 tyh = __float2half2_rn(tyf);

            // A path: x-lerp both rows, then y-lerp, all in half2
            __half2 a0 = *(__half2*)&w0.x;
            __half2 a1 = *(__half2*)&w0.y;
            __half2 b0h = *(__half2*)&w1.x;
            __half2 b1h = *(__half2*)&w1.y;
            __half2 r0 = __hfma2(txh, __hsub2(a1, a0), a0);
            __half2 r1 = __hfma2(txh, __hsub2(b1h, b0h), b0h);
            __half2 ry = __hfma2(tyh, __hsub2(r1, r0), r0);
            float2 rf = __half22float2(ry);
            s0 += rf.x;
            s1 += rf.y;

            // C path: y-lerp in half2 (lanes are x0,x1), then x-lerp in fp32
            __half2 zy = __hfma2(tyh, __hsub2(z1, z0), z0);
            float2 zf = __half22float2(zy);
            s2 += zf.x;
            s2 = fmaf(txf, zf.y - zf.x, s2);
        }

        fb[gidx]          = fmaf(wgt, s0, bs);
        fb[gidx + HW]     = fmaf(wgt, s1, bs);
        fb[gidx + 2 * HW] = fmaf(wgt, s2, bs);
    }
}

extern "C" void kernel_launch(void* const* d_in, const int* in_sizes, int n_in,
                              void* d_out, int out_size)
{
    const float* fake_S  = (const float*)d_in[0];
    const float* blurmap = (const float*)d_in[1];
    const float* weight  = (const float*)d_in[2];
    const float* bias    = (const float*)d_in[3];

    float* out_fb  = (float*)d_out;
    float* out_off = (float*)d_out + (size_t)BATCH * 3 * HW;

    const int smem = TDY * TDX * 12;   // 89,856 B
    static bool configured = false;
    if (!configured) {
        cudaFuncSetAttribute(blurnet_kernel,
                             cudaFuncAttributeMaxDynamicSharedMemorySize, smem);
        configured = true;
    }

    dim3 grid(W / TX, H / TY, BATCH);   // (4, 8, 8) = 256 CTAs
    blurnet_kernel<<<grid, NTHREADS, smem>>>(fake_S, blurmap, weight, bias,
                                             out_fb, out_off);
}

// round 15
// speedup vs baseline: 1.0667x; 1.0667x over previous
#include <cuda_runtime.h>
#include <cuda_fp16.h>

// BlurNet: fake_B = w * mean_k bilinear(fake_S, pix + t_k*20*blurmap) + bias
//          offsets_flat[b, 2k+c] = t_k * 20 * blurmap[b, c],  t_k = (7-k)/7
// B=8, C=3, H=W=256. Output: fake_B (B*3*H*W) then offsets (B*30*H*W), f32.
//
// R15 = R13 body (64x32 tile, fp16 pair-dup gather, half2 lerp, interleaved
// offset STGs) at 384 threads / 2 CTAs => 24 warps/SM x 85 regs. Probing the
// untested point on the warps-x-regs frontier: 32w/64r=30.1, 24w/72r(old fat
// body)=33.0, 16w/120r=32.4. The lean half2 body at 85 regs can batch ~2x
// more LDS per warp than at 64 regs.

#define H 256
#define W 256
#define HW (H * W)
#define BATCH 8
#define TX 64
#define TY 32
#define HALO 20
#define TDX (TX + 2 * HALO)      // 104
#define TDY (TY + 2 * HALO)      // 72
#define NTHREADS 384

__global__ __launch_bounds__(NTHREADS, 2)
void blurnet_kernel(const float* __restrict__ fake_S,
                    const float* __restrict__ blurmap,
                    const float* __restrict__ weight,
                    const float* __restrict__ bias,
                    float* __restrict__ out_fb,
                    float* __restrict__ out_off)
{
    extern __shared__ __align__(16) unsigned char smem_raw[];
    uint2*   Ap = (uint2*)smem_raw;                         // 72*104*8 = 59904 B
    __half2* Cp = (__half2*)(smem_raw + TDY * TDX * 8);     // 72*104*4 = 29952 B

    const int tx0 = blockIdx.x * TX;
    const int ty0 = blockIdx.y * TY;
    const int b   = blockIdx.z;
    const int tid = threadIdx.x;

    const float* img  = fake_S  + (size_t)b * 3 * HW;
    const float* bm   = blurmap + (size_t)b * 2 * HW;
    float*       fb   = out_fb  + (size_t)b * 3 * HW;
    float*       offp = out_off + (size_t)b * 30 * HW;

    // ---- Halo fill: R3-proven scalar path ----
    #pragma unroll 3
    for (int p = tid; p < TDY * TDX; p += NTHREADS) {
        int r  = p / TDX;
        int cc = p - r * TDX;
        int gy = ty0 - HALO + r;
        int gx = tx0 - HALO + cc;
        float v0 = 0.f, v1 = 0.f, v2 = 0.f;   // (gy, gx)
        float u0 = 0.f, u1 = 0.f, u2 = 0.f;   // (gy, gx+1)
        bool rowok = (unsigned)gy < (unsigned)H;
        if (rowok && (unsigned)gx < (unsigned)W) {
            int gi = gy * W + gx;
            v0 = __ldg(img + gi);
            v1 = __ldg(img + gi + HW);
            v2 = __ldg(img + gi + 2 * HW);
        }
        if (rowok && (unsigned)(gx + 1) < (unsigned)W) {
            int gi = gy * W + gx + 1;
            u0 = __ldg(img + gi);
            u1 = __ldg(img + gi + HW);
            u2 = __ldg(img + gi + 2 * HW);
        }
        __half2 lo = __floats2half2_rn(v0, v1);
        __half2 hi = __floats2half2_rn(u0, u1);
        uint2 w;
        w.x = *(unsigned int*)&lo;
        w.y = *(unsigned int*)&hi;
        Ap[p] = w;
        Cp[p] = __floats2half2_rn(v2, u2);
    }
    __syncthreads();

    const float wgt = __ldg(weight) * (1.0f / 15.0f);
    const float bs  = __ldg(bias);

    // ---- Blur loop: ragged 2048 px over 384 threads (6 iters, last 1/3) ----
    #pragma unroll 1
    for (int p = tid; p < TX * TY; p += NTHREADS) {
        int yl = p >> 6;              // 0..31
        int xl = p & 63;              // 0..63
        int gy = ty0 + yl;
        int gx = tx0 + xl;
        int gidx = gy * W + gx;

        float ob0 = 20.0f * __ldg(bm + gidx);        // dy scale (ch0)
        float ob1 = 20.0f * __ldg(bm + gidx + HW);   // dx scale (ch1)

        // k = 7 (t = 0): exact center sample, zero offsets
        int cbase = (yl + HALO) * TDX + (xl + HALO);
        uint2 cw = Ap[cbase];
        float2 cl = __half22float2(*(__half2*)&cw.x);
        float2 cz = __half22float2(Cp[cbase]);
        float s0 = cl.x, s1 = cl.y, s2 = cz.x;
        offp[14 * HW + gidx] = 0.f;
        offp[15 * HW + gidx] = 0.f;

        #pragma unroll
        for (int k = 0; k < 15; k++) {
            if (k == 7) continue;
            const float t = (float)(7 - k) / 7.0f;   // compile-time constant
            float oy = t * ob0;
            float ox = t * ob1;
            offp[(2 * k) * HW + gidx]     = oy;
            offp[(2 * k + 1) * HW + gidx] = ox;

            float fy  = (float)gy + oy;              // global coords = ref rounding
            float fx  = (float)gx + ox;
            float fy0 = floorf(fy);
            float fx0 = floorf(fx);
            float tyf = fy - fy0;
            float txf = fx - fx0;
            int iy = (int)fy0 - ty0 + HALO;
            int ix = (int)fx0 - tx0 + HALO;
            int base2 = iy * TDX + ix;

            uint2   w0 = Ap[base2];           // row y0: (c0,c1)@x0,x1
            uint2   w1 = Ap[base2 + TDX];     // row y1
            __half2 z0 = Cp[base2];           // c2@(x0,x1), row y0
            __half2 z1 = Cp[base2 + TDX];     // row y1

            __half2 txh = __float2half2_rn(txf);
            __half2 tyh = __float2half2_rn(tyf);

            // A path: x-lerp both rows, then y-lerp, all in half2
            __half2 a0 = *(__half2*)&w0.x;
            __half2 a1 = *(__half2*)&w0.y;
            __half2 b0h = *(__half2*)&w1.x;
            __half2 b1h = *(__half2*)&w1.y;
            __half2 r0 = __hfma2(txh, __hsub2(a1, a0), a0);
            __half2 r1 = __hfma2(txh, __hsub2(b1h, b0h), b0h);
            __half2 ry = __hfma2(tyh, __hsub2(r1, r0), r0);
            float2 rf = __half22float2(ry);
            s0 += rf.x;
            s1 += rf.y;

            // C path: y-lerp in half2 (lanes are x0,x1), then x-lerp in fp32
            __half2 zy = __hfma2(tyh, __hsub2(z1, z0), z0);
            float2 zf = __half22float2(zy);
            s2 += zf.x;
            s2 = fmaf(txf, zf.y - zf.x, s2);
        }

        fb[gidx]          = fmaf(wgt, s0, bs);
        fb[gidx + HW]     = fmaf(wgt, s1, bs);
        fb[gidx + 2 * HW] = fmaf(wgt, s2, bs);
    }
}

extern "C" void kernel_launch(void* const* d_in, const int* in_sizes, int n_in,
                              void* d_out, int out_size)
{
    const float* fake_S  = (const float*)d_in[0];
    const float* blurmap = (const float*)d_in[1];
    const float* weight  = (const float*)d_in[2];
    const float* bias    = (const float*)d_in[3];

    float* out_fb  = (float*)d_out;
    float* out_off = (float*)d_out + (size_t)BATCH * 3 * HW;

    const int smem = TDY * TDX * 12;   // 89,856 B
    static bool configured = false;
    if (!configured) {
        cudaFuncSetAttribute(blurnet_kernel,
                             cudaFuncAttributeMaxDynamicSharedMemorySize, smem);
        configured = true;
    }

    dim3 grid(W / TX, H / TY, BATCH);   // (4, 8, 8) = 256 CTAs
    blurnet_kernel<<<grid, NTHREADS, smem>>>(fake_S, blurmap, weight, bias,
                                             out_fb, out_off);
}